// round 11
// baseline (speedup 1.0000x reference)
#include <cuda_runtime.h>
#include <float.h>

// ---------------------------------------------------------------------------
// FeatPropagation via uniform-grid EXACT k=3 NN + inverse-distance interp.
//
// R11: QUERY-MAJOR dense phase. R10 proved the cell-block scan burns ~110us
// on warp-rounding waste (cells hold 5-20 queries; their warps scan ~500-900
// candidates at <50% lane utilization). Now each WARP owns 32 consecutive
// SORTED queries (100% active lanes), computes the union cell box (+1 ring),
// stages it into a private SMEM slice in 256-candidate chunks, and scans.
// Union box contains each query's own 3x3x3 box, so the conservative own-box
// stop bound is unchanged. Oversized union boxes (rare sparse wraps) and
// queries failing the bound go to g_far (warp-per-query exclusive shells).
//
// Ranking stays BIT-EXACT vs the JAX reference (GEMM-form d2 with explicit
// rounding intrinsics); (d2, index) lexicographic insert == top_k
// lowest-index tie-break, independent of scatter/list order.
// ---------------------------------------------------------------------------

#define G      16
#define G3     (G * G * G)
#define GLO    (-4.0f)
#define HV     0.5f
#define INVH   2.0f
#define MAXB   8
#define MARGIN 2e-4f

// point grid
__device__ int    g_cnt[MAXB * G3];
__device__ int    g_start[MAXB * (G3 + 1)];
__device__ int    g_cur[MAXB * G3];
__device__ float4 g_pts[1 << 15];
__device__ int    g_pid[1 << 15];
// query grid
__device__ int    g_qcnt[MAXB * G3];
__device__ int    g_qstart[MAXB * (G3 + 1)];
__device__ int    g_qcur[MAXB * G3];
__device__ float4 g_qpts[1 << 17];
__device__ int    g_qid[1 << 17];
// unresolved-query list
__device__ int    g_nfar;
__device__ int    g_far[1 << 17];

#define CAPQ (3 * (1 << 17))
__device__ int   g_idx[CAPQ];          // by SORTED slot
__device__ float g_w[CAPQ];            // by SORTED slot

__device__ __forceinline__ int cell1(float v) {
    int c = (int)floorf((v - GLO) * INVH);
    return min(max(c, 0), G - 1);
}

__global__ void zero_kernel(int cells) {
    int i = blockIdx.x * blockDim.x + threadIdx.x;
    if (i < cells) { g_cnt[i] = 0; g_qcnt[i] = 0; }
    if (i == 0) g_nfar = 0;
}

// fused: first Ntot entries are points, next Mtot are queries
__global__ void count_all(const float* __restrict__ xyz,
                          const float* __restrict__ qxyz,
                          int N, int Ntot, int M, int Mtot) {
    int i = blockIdx.x * blockDim.x + threadIdx.x;
    if (i < Ntot) {
        int b = i / N;
        float x = xyz[3 * i], y = xyz[3 * i + 1], z = xyz[3 * i + 2];
        atomicAdd(g_cnt + b * G3 + (cell1(z) * G + cell1(y)) * G + cell1(x), 1);
    } else if (i < Ntot + Mtot) {
        int j = i - Ntot;
        int b = j / M;
        float x = qxyz[3 * j], y = qxyz[3 * j + 1], z = qxyz[3 * j + 2];
        atomicAdd(g_qcnt + b * G3 + (cell1(z) * G + cell1(y)) * G + cell1(x), 1);
    }
}

__global__ void __launch_bounds__(1024) scan_kernel() {
    const int b = blockIdx.x;
    int* cnt   = (blockIdx.y ? g_qcnt   : g_cnt)   + b * G3;
    int* start = (blockIdx.y ? g_qstart : g_start) + b * (G3 + 1);
    int* cur   = (blockIdx.y ? g_qcur   : g_cur)   + b * G3;

    const int tid = threadIdx.x;
    __shared__ int sm[1024];

    const int lo = tid * 4;
    int c0 = cnt[lo], c1 = cnt[lo + 1], c2 = cnt[lo + 2], c3 = cnt[lo + 3];
    const int sum = c0 + c1 + c2 + c3;
    sm[tid] = sum;
    __syncthreads();
    for (int off = 1; off < 1024; off <<= 1) {
        int v = (tid >= off) ? sm[tid - off] : 0;
        __syncthreads();
        sm[tid] += v;
        __syncthreads();
    }
    int run = sm[tid] - sum;
    start[lo]     = run;  cur[lo]     = run;  run += c0;
    start[lo + 1] = run;  cur[lo + 1] = run;  run += c1;
    start[lo + 2] = run;  cur[lo + 2] = run;  run += c2;
    start[lo + 3] = run;  cur[lo + 3] = run;
    if (tid == 1023) start[G3] = sm[1023];
}

__global__ void scatter_all(const float* __restrict__ xyz,
                            const float* __restrict__ qxyz,
                            int N, int Ntot, int M, int Mtot) {
    int i = blockIdx.x * blockDim.x + threadIdx.x;
    if (i < Ntot) {
        int b = i / N;
        float x = xyz[3 * i], y = xyz[3 * i + 1], z = xyz[3 * i + 2];
        int c = (cell1(z) * G + cell1(y)) * G + cell1(x);
        int pos = atomicAdd(g_cur + b * G3 + c, 1);
        float s2 = __fadd_rn(__fadd_rn(__fmul_rn(x, x), __fmul_rn(y, y)),
                             __fmul_rn(z, z));
        g_pts[b * N + pos] = make_float4(x, y, z, s2);
        g_pid[b * N + pos] = i;
    } else if (i < Ntot + Mtot) {
        int j = i - Ntot;
        int b = j / M;
        float x = qxyz[3 * j], y = qxyz[3 * j + 1], z = qxyz[3 * j + 2];
        int c = (cell1(z) * G + cell1(y)) * G + cell1(x);
        int pos = atomicAdd(g_qcur + b * G3 + c, 1);
        float s2 = __fadd_rn(__fadd_rn(__fmul_rn(x, x), __fmul_rn(y, y)),
                             __fmul_rn(z, z));
        g_qpts[b * M + pos] = make_float4(x, y, z, s2);
        g_qid [b * M + pos] = j;
    }
}

// ---------------------------------------------------------------------------
// knn_near: warp = 32 consecutive sorted queries. Union box staged in SMEM.
// ---------------------------------------------------------------------------
#define NEAR_T  128                    // 4 warps/block
#define NWARPS  (NEAR_T / 32)
#define WCHUNK  256                    // candidates per staged chunk
#define MAXROW  96

__global__ void __launch_bounds__(NEAR_T)
knn_near(int N, int M)
{
    const int b    = blockIdx.y;
    const int warp = threadIdx.x >> 5;
    const int lane = threadIdx.x & 31;
    const int qi   = blockIdx.x * NEAR_T + warp * 32 + lane;   // within batch
    const bool act = (qi < M);
    if (__ballot_sync(0xFFFFFFFFu, act) == 0) return;

    const int bs    = b * (G3 + 1);
    const int pbase = b * N;
    const int qslot = b * M + min(qi, M - 1);

    __shared__ float4 spts[NWARPS][WCHUNK];
    __shared__ int    sid [NWARPS][WCHUNK];
    __shared__ int    rS  [NWARPS][MAXROW];
    __shared__ int    rE  [NWARPS][MAXROW];

    const float4 Q = g_qpts[qslot];
    const float qx = Q.x, qy = Q.y, qz = Q.z, q2 = Q.w;
    const int cx = cell1(qx), cy = cell1(qy), cz = cell1(qz);

    // warp union cell box (+1 ring), inactive lanes neutral
    const int Zlo = max(__reduce_min_sync(0xFFFFFFFFu, act ? cz :  1000) - 1, 0);
    const int Zhi = min(__reduce_max_sync(0xFFFFFFFFu, act ? cz : -1000) + 1, G - 1);
    const int Ylo = max(__reduce_min_sync(0xFFFFFFFFu, act ? cy :  1000) - 1, 0);
    const int Yhi = min(__reduce_max_sync(0xFFFFFFFFu, act ? cy : -1000) + 1, G - 1);
    const int Xlo = max(__reduce_min_sync(0xFFFFFFFFu, act ? cx :  1000) - 1, 0);
    const int Xhi = min(__reduce_max_sync(0xFFFFFFFFu, act ? cx : -1000) + 1, G - 1);

    const int Yspan = Yhi - Ylo + 1;
    const int nrows = (Zhi - Zlo + 1) * Yspan;
    if (nrows > MAXROW) {               // pathological sparse wrap: punt all
        if (act) g_far[atomicAdd(&g_nfar, 1)] = qslot;
        return;
    }

    for (int t = lane; t < nrows; t += 32) {
        const int z = Zlo + t / Yspan;
        const int y = Ylo + t % Yspan;
        const int row = (z * G + y) * G;
        rS[warp][t] = g_start[bs + row + Xlo];
        rE[warp][t] = g_start[bs + row + Xhi + 1];
    }
    __syncwarp();

    float d0 = 1e30f, d1 = 1e30f, d2v = 1e30f;
    int   i0 = -1,    i1 = -1,    i2 = -1;

    auto ins = [&](float dd, int id) {
        if (dd < d2v || (dd == d2v && id < i2)) {
            if (dd < d1 || (dd == d1 && id < i1)) {
                d2v = d1; i2 = i1;
                if (dd < d0 || (dd == d0 && id < i0)) {
                    d1 = d0; i1 = i0; d0 = dd; i0 = id;
                } else { d1 = dd; i1 = id; }
            } else { d2v = dd; i2 = id; }
        }
    };
    auto dist2 = [&](const float4& P) -> float {
        const float cross = __fmaf_rn(qz, P.z,
                              __fmaf_rn(qy, P.y, __fmul_rn(qx, P.x)));
        return __fmaf_rn(-2.0f, cross, __fadd_rn(q2, P.w));
    };

    // warp-scalar chunked fill + scan
    int slot = 0;
    int pos  = rS[warp][0];
    while (slot < nrows) {
        int filled = 0;
        while (slot < nrows && filled < WCHUNK) {
            const int s = rS[warp][slot], e = rE[warp][slot];
            const int p0 = max(pos, s);
            const int avail = e - p0;
            if (avail <= 0) {
                slot++;
                if (slot < nrows) pos = rS[warp][slot];
                continue;
            }
            const int take = min(avail, WCHUNK - filled);
            for (int i = lane; i < take; i += 32) {
                spts[warp][filled + i] = g_pts[pbase + p0 + i];
                sid [warp][filled + i] = g_pid[pbase + p0 + i];
            }
            filled += take;
            pos = p0 + take;
            if (pos >= e) {
                slot++;
                if (slot < nrows) pos = rS[warp][slot];
            }
        }
        __syncwarp();

        if (act) {
            const int k4 = filled & ~3;
            for (int j = 0; j < k4; j += 4) {
                const float dd0 = dist2(spts[warp][j + 0]);
                const float dd1 = dist2(spts[warp][j + 1]);
                const float dd2 = dist2(spts[warp][j + 2]);
                const float dd3 = dist2(spts[warp][j + 3]);
                const float gm  = fminf(fminf(dd0, dd1), fminf(dd2, dd3));
                if (gm <= d2v) {
                    ins(dd0, sid[warp][j + 0]);
                    ins(dd1, sid[warp][j + 1]);
                    ins(dd2, sid[warp][j + 2]);
                    ins(dd3, sid[warp][j + 3]);
                }
            }
            for (int j = k4; j < filled; j++)
                ins(dist2(spts[warp][j]), sid[warp][j]);
        }
        __syncwarp();
    }

    if (act) {
        // stop check on the query's OWN r=1 box (contained in staged union)
        bool done = false;
        const float fxl = (cx - 1 <= 0)     ? 1e30f : qx - (GLO + (cx - 1) * HV);
        const float fxh = (cx + 1 >= G - 1) ? 1e30f : (GLO + (cx + 2) * HV) - qx;
        const float fyl = (cy - 1 <= 0)     ? 1e30f : qy - (GLO + (cy - 1) * HV);
        const float fyh = (cy + 1 >= G - 1) ? 1e30f : (GLO + (cy + 2) * HV) - qy;
        const float fzl = (cz - 1 <= 0)     ? 1e30f : qz - (GLO + (cz - 1) * HV);
        const float fzh = (cz + 1 >= G - 1) ? 1e30f : (GLO + (cz + 2) * HV) - qz;
        const float lb  = fminf(fminf(fminf(fxl, fxh), fminf(fyl, fyh)),
                                fminf(fzl, fzh));
        if (lb >= 1e29f) done = true;
        else if (i2 >= 0 && lb > 0.0f && d2v + MARGIN <= lb * lb) done = true;

        if (done) {
            const float e0 = sqrtf(fmaxf(d0,  1e-12f));
            const float e1 = sqrtf(fmaxf(d1,  1e-12f));
            const float e2 = sqrtf(fmaxf(d2v, 1e-12f));
            const float r0 = __fdiv_rn(1.0f, __fadd_rn(e0, 1e-8f));
            const float r1 = __fdiv_rn(1.0f, __fadd_rn(e1, 1e-8f));
            const float r2 = __fdiv_rn(1.0f, __fadd_rn(e2, 1e-8f));
            const float s  = __fadd_rn(__fadd_rn(r0, r1), r2);
            const int base  = 3 * qslot;
            g_idx[base + 0] = i0;
            g_idx[base + 1] = i1;
            g_idx[base + 2] = i2;
            g_w[base + 0]   = __fdiv_rn(r0, s);
            g_w[base + 1]   = __fdiv_rn(r1, s);
            g_w[base + 2]   = __fdiv_rn(r2, s);
        } else {
            g_far[atomicAdd(&g_nfar, 1)] = qslot;
        }
    }
}

// ---------------------------------------------------------------------------
// knn_far: warp per unresolved query; mutually exclusive shells (R10-fixed).
// ---------------------------------------------------------------------------
#define FAR_T 256

__global__ void __launch_bounds__(FAR_T)
knn_far(int N, int M)
{
    const int nfar  = g_nfar;
    const int gwarp = (blockIdx.x * FAR_T + threadIdx.x) >> 5;
    const int lane  = threadIdx.x & 31;
    const int nwarp = (gridDim.x * FAR_T) >> 5;

    for (int i = gwarp; i < nfar; i += nwarp) {
        const int qslot = g_far[i];
        const int b     = qslot / M;
        const float4 Q  = g_qpts[qslot];
        const float qx = Q.x, qy = Q.y, qz = Q.z, q2 = Q.w;
        const int cx = cell1(qx), cy = cell1(qy), cz = cell1(qz);
        const int bs = b * (G3 + 1), pbase = b * N;

        float d0 = 1e30f, d1 = 1e30f, d2v = 1e30f;
        int   i0 = -1,    i1 = -1,    i2 = -1;

        auto ins = [&](float dd, int id) {
            if (dd < d2v || (dd == d2v && id < i2)) {
                if (dd < d1 || (dd == d1 && id < i1)) {
                    d2v = d1; i2 = i1;
                    if (dd < d0 || (dd == d0 && id < i0)) {
                        d1 = d0; i1 = i0; d0 = dd; i0 = id;
                    } else { d1 = dd; i1 = id; }
                } else { d2v = dd; i2 = id; }
            }
        };
        auto dist2 = [&](const float4& P) -> float {
            const float cross = __fmaf_rn(qz, P.z,
                                  __fmaf_rn(qy, P.y, __fmul_rn(qx, P.x)));
            return __fmaf_rn(-2.0f, cross, __fadd_rn(q2, P.w));
        };
        auto scanrange = [&](int s, int e) {
            for (int p = s; p < e; p++) {
                const float4 P = g_pts[pbase + p];
                ins(dist2(P), g_pid[pbase + p]);
            }
        };

        float m0 = 1e30f, m1 = 1e30f, m2 = 1e30f;
        int   j0 = -1,    j1 = -1,    j2 = -1;
        auto insM = [&](float dd, int id) {
            if (dd < m2 || (dd == m2 && id < j2)) {
                if (dd < m1 || (dd == m1 && id < j1)) {
                    m2 = m1; j2 = j1;
                    if (dd < m0 || (dd == m0 && id < j0)) {
                        m1 = m0; j1 = j0; m0 = dd; j0 = id;
                    } else { m1 = dd; j1 = id; }
                } else { m2 = dd; j2 = id; }
            }
        };

        for (int rr = 0; ; rr++) {
            const int W = 2 * rr + 1;
            const int nrow = W * W;
            for (int t = lane; t < nrow; t += 32) {
                const int dz = t / W - rr, dy = t % W - rr;
                const int z = cz + dz, y = cy + dy;
                if (z < 0 || z >= G || y < 0 || y >= G) continue;
                const int row  = (z * G + y) * G;
                // EXCLUSIVE shell: boundary rows full x-span only.
                const bool full = (dz == -rr) || (dz == rr)
                               || (dy == -rr) || (dy == rr);
                if (full) {
                    const int xlo = max(cx - rr, 0), xhi = min(cx + rr, G - 1);
                    scanrange(__ldg(&g_start[bs + row + xlo]),
                              __ldg(&g_start[bs + row + xhi + 1]));
                } else {
                    if (cx - rr >= 0)
                        scanrange(__ldg(&g_start[bs + row + cx - rr]),
                                  __ldg(&g_start[bs + row + cx - rr + 1]));
                    if (cx + rr <= G - 1)
                        scanrange(__ldg(&g_start[bs + row + cx + rr]),
                                  __ldg(&g_start[bs + row + cx + rr + 1]));
                }
            }

            m0 = d0; m1 = d1; m2 = d2v; j0 = i0; j1 = i1; j2 = i2;
            for (int off = 16; off; off >>= 1) {
                const float b0 = __shfl_down_sync(0xFFFFFFFFu, m0, off);
                const float b1 = __shfl_down_sync(0xFFFFFFFFu, m1, off);
                const float b2 = __shfl_down_sync(0xFFFFFFFFu, m2, off);
                const int   c0 = __shfl_down_sync(0xFFFFFFFFu, j0, off);
                const int   c1 = __shfl_down_sync(0xFFFFFFFFu, j1, off);
                const int   c2 = __shfl_down_sync(0xFFFFFFFFu, j2, off);
                if (lane < off) { insM(b0, c0); insM(b1, c1); insM(b2, c2); }
            }
            const float m2b = __shfl_sync(0xFFFFFFFFu, m2, 0);
            const int   j2b = __shfl_sync(0xFFFFFFFFu, j2, 0);

            const float fxl = (cx - rr <= 0)     ? 1e30f : qx - (GLO + (cx - rr) * HV);
            const float fxh = (cx + rr >= G - 1) ? 1e30f : (GLO + (cx + rr + 1) * HV) - qx;
            const float fyl = (cy - rr <= 0)     ? 1e30f : qy - (GLO + (cy - rr) * HV);
            const float fyh = (cy + rr >= G - 1) ? 1e30f : (GLO + (cy + rr + 1) * HV) - qy;
            const float fzl = (cz - rr <= 0)     ? 1e30f : qz - (GLO + (cz - rr) * HV);
            const float fzh = (cz + rr >= G - 1) ? 1e30f : (GLO + (cz + rr + 1) * HV) - qz;
            const float lb  = fminf(fminf(fminf(fxl, fxh), fminf(fyl, fyh)),
                                    fminf(fzl, fzh));
            if (lb >= 1e29f) break;
            if (j2b >= 0 && lb > 0.0f && m2b + MARGIN <= lb * lb) break;
        }

        if (lane == 0) {
            const float e0 = sqrtf(fmaxf(m0, 1e-12f));
            const float e1 = sqrtf(fmaxf(m1, 1e-12f));
            const float e2 = sqrtf(fmaxf(m2, 1e-12f));
            const float r0 = __fdiv_rn(1.0f, __fadd_rn(e0, 1e-8f));
            const float r1 = __fdiv_rn(1.0f, __fadd_rn(e1, 1e-8f));
            const float r2 = __fdiv_rn(1.0f, __fadd_rn(e2, 1e-8f));
            const float s  = __fadd_rn(__fadd_rn(r0, r1), r2);
            const int base  = 3 * qslot;
            g_idx[base + 0] = j0;
            g_idx[base + 1] = j1;
            g_idx[base + 2] = j2;
            g_w[base + 0]   = __fdiv_rn(r0, s);
            g_w[base + 1]   = __fdiv_rn(r1, s);
            g_w[base + 2]   = __fdiv_rn(r2, s);
        }
    }
}

// interp walks SORTED order; output row via g_qid
__global__ void __launch_bounds__(256)
interp_kernel(const float* __restrict__ feat, float* __restrict__ out,
              int C4, int total)
{
    const int t = blockIdx.x * 256 + threadIdx.x;
    if (t >= total) return;

    const int j  = t / C4;
    const int cg = t - j * C4;

    const int   base = 3 * j;
    const int   i0 = g_idx[base + 0];
    const int   i1 = g_idx[base + 1];
    const int   i2 = g_idx[base + 2];
    const float w0 = g_w[base + 0];
    const float w1 = g_w[base + 1];
    const float w2 = g_w[base + 2];
    const int   qid = g_qid[j];

    const float4* f = reinterpret_cast<const float4*>(feat);
    const float4 a = __ldg(f + (size_t)i0 * C4 + cg);
    const float4 b = __ldg(f + (size_t)i1 * C4 + cg);
    const float4 c = __ldg(f + (size_t)i2 * C4 + cg);

    float4 o;
    o.x = fmaf(w2, c.x, fmaf(w1, b.x, w0 * a.x));
    o.y = fmaf(w2, c.y, fmaf(w1, b.y, w0 * a.y));
    o.z = fmaf(w2, c.z, fmaf(w1, b.z, w0 * a.z));
    o.w = fmaf(w2, c.w, fmaf(w1, b.w, w0 * a.w));

    reinterpret_cast<float4*>(out)[(size_t)qid * C4 + cg] = o;
}

extern "C" void kernel_launch(void* const* d_in, const int* in_sizes, int n_in,
                              void* d_out, int out_size)
{
    const float* xyz     = (const float*)d_in[0];
    const float* new_xyz = (const float*)d_in[1];
    const float* feat    = (const float*)d_in[2];

    const int B    = in_sizes[3];
    const int Ntot = in_sizes[0] / 3;
    const int Mtot = in_sizes[1] / 3;
    const int N    = Ntot / B;
    const int M    = Mtot / B;
    const int C    = in_sizes[2] / Ntot;

    const int cells = B * G3;
    const int tot   = Ntot + Mtot;
    zero_kernel<<<(cells + 255) / 256, 256>>>(cells);
    count_all<<<(tot + 255) / 256, 256>>>(xyz, new_xyz, N, Ntot, M, Mtot);
    scan_kernel<<<dim3(B, 2), 1024>>>();
    scatter_all<<<(tot + 255) / 256, 256>>>(xyz, new_xyz, N, Ntot, M, Mtot);

    knn_near<<<dim3((M + NEAR_T - 1) / NEAR_T, B), NEAR_T>>>(N, M);
    knn_far<<<256, FAR_T>>>(N, M);

    const int C4    = C / 4;
    const int total = Mtot * C4;
    interp_kernel<<<(total + 255) / 256, 256>>>(feat, (float*)d_out, C4, total);
}

// round 12
// speedup vs baseline: 1.4239x; 1.4239x over previous
#include <cuda_runtime.h>
#include <float.h>

// ---------------------------------------------------------------------------
// FeatPropagation via uniform-grid EXACT k=3 NN + inverse-distance interp.
//
// R12 == R7 (best: 157.7us) with the build phase fused (count_all /
// scatter_all handle points+queries together; counter zeroing moved to a
// TAIL launch — valid since __device__ globals are statically zero-init, so
// every invocation starts from zeroed counters). This also places knn_cell
// at kernel-launch #4, which is the launch ncu captures -> next round we
// finally profile the hot kernel.
//
// Ranking stays BIT-EXACT vs the JAX reference (GEMM-form d2 with explicit
// rounding intrinsics); (d2, index) lexicographic insert == top_k
// lowest-index tie-break, independent of scatter order. Stop bound is
// conservative (MARGIN >> reference rounding error) -> exact result.
// ---------------------------------------------------------------------------

#define G      16
#define G3     (G * G * G)
#define GLO    (-4.0f)
#define HV     0.5f
#define INVH   2.0f
#define MAXB   8
#define MARGIN 2e-4f

// point grid
__device__ int    g_cnt[MAXB * G3];
__device__ int    g_start[MAXB * (G3 + 1)];
__device__ int    g_cur[MAXB * G3];
__device__ float4 g_pts[1 << 15];      // sorted points {x,y,z,s2}
__device__ int    g_pid[1 << 15];      // sorted slot -> original global index
// query grid
__device__ int    g_qcnt[MAXB * G3];
__device__ int    g_qstart[MAXB * (G3 + 1)];
__device__ int    g_qcur[MAXB * G3];
__device__ float4 g_qpts[1 << 17];     // sorted queries {x,y,z,q2}
__device__ int    g_qid[1 << 17];      // sorted slot -> original global index

#define CAPQ (3 * (1 << 17))
__device__ int   g_idx[CAPQ];          // by ORIGINAL query id (R7 layout)
__device__ float g_w[CAPQ];

__device__ __forceinline__ int cell1(float v) {
    int c = (int)floorf((v - GLO) * INVH);
    return min(max(c, 0), G - 1);
}

// fused histogram: first Ntot ids are points, next Mtot are queries
__global__ void count_all(const float* __restrict__ xyz,
                          const float* __restrict__ qxyz,
                          int N, int Ntot, int M, int Mtot) {
    int i = blockIdx.x * blockDim.x + threadIdx.x;
    if (i < Ntot) {
        int b = i / N;
        float x = xyz[3 * i], y = xyz[3 * i + 1], z = xyz[3 * i + 2];
        atomicAdd(g_cnt + b * G3 + (cell1(z) * G + cell1(y)) * G + cell1(x), 1);
    } else if (i < Ntot + Mtot) {
        int j = i - Ntot;
        int b = j / M;
        float x = qxyz[3 * j], y = qxyz[3 * j + 1], z = qxyz[3 * j + 2];
        atomicAdd(g_qcnt + b * G3 + (cell1(z) * G + cell1(y)) * G + cell1(x), 1);
    }
}

// grid (B, 2): y==0 point counters, y==1 query counters. 4 cells/thread.
__global__ void __launch_bounds__(1024) scan_kernel() {
    const int b = blockIdx.x;
    int* cnt   = (blockIdx.y ? g_qcnt   : g_cnt)   + b * G3;
    int* start = (blockIdx.y ? g_qstart : g_start) + b * (G3 + 1);
    int* cur   = (blockIdx.y ? g_qcur   : g_cur)   + b * G3;

    const int tid = threadIdx.x;
    __shared__ int sm[1024];

    const int lo = tid * 4;
    int c0 = cnt[lo], c1 = cnt[lo + 1], c2 = cnt[lo + 2], c3 = cnt[lo + 3];
    const int sum = c0 + c1 + c2 + c3;
    sm[tid] = sum;
    __syncthreads();
    for (int off = 1; off < 1024; off <<= 1) {            // Hillis-Steele
        int v = (tid >= off) ? sm[tid - off] : 0;
        __syncthreads();
        sm[tid] += v;
        __syncthreads();
    }
    int run = sm[tid] - sum;
    start[lo]     = run;  cur[lo]     = run;  run += c0;
    start[lo + 1] = run;  cur[lo + 1] = run;  run += c1;
    start[lo + 2] = run;  cur[lo + 2] = run;  run += c2;
    start[lo + 3] = run;  cur[lo + 3] = run;
    if (tid == 1023) start[G3] = sm[1023];
}

__global__ void scatter_all(const float* __restrict__ xyz,
                            const float* __restrict__ qxyz,
                            int N, int Ntot, int M, int Mtot) {
    int i = blockIdx.x * blockDim.x + threadIdx.x;
    if (i < Ntot) {
        int b = i / N;
        float x = xyz[3 * i], y = xyz[3 * i + 1], z = xyz[3 * i + 2];
        int c = (cell1(z) * G + cell1(y)) * G + cell1(x);
        int pos = atomicAdd(g_cur + b * G3 + c, 1);
        float s2 = __fadd_rn(__fadd_rn(__fmul_rn(x, x), __fmul_rn(y, y)),
                             __fmul_rn(z, z));
        g_pts[b * N + pos] = make_float4(x, y, z, s2);
        g_pid[b * N + pos] = i;
    } else if (i < Ntot + Mtot) {
        int j = i - Ntot;
        int b = j / M;
        float x = qxyz[3 * j], y = qxyz[3 * j + 1], z = qxyz[3 * j + 2];
        int c = (cell1(z) * G + cell1(y)) * G + cell1(x);
        int pos = atomicAdd(g_qcur + b * G3 + c, 1);
        float s2 = __fadd_rn(__fadd_rn(__fmul_rn(x, x), __fmul_rn(y, y)),
                             __fmul_rn(z, z));
        g_qpts[b * M + pos] = make_float4(x, y, z, s2);
        g_qid [b * M + pos] = j;
    }
}

// tail: zero counters for the NEXT invocation (statics start zeroed)
__global__ void zero_tail(int cells) {
    int i = blockIdx.x * blockDim.x + threadIdx.x;
    if (i < cells) { g_cnt[i] = 0; g_qcnt[i] = 0; }
}

// ---------------------------------------------------------------------------
// knn_cell: R7 verbatim. One block per (cell, batch); 3x3x3 box staged in
// SMEM; per-thread fallback ring walk from r=2 for queries failing the bound.
// ---------------------------------------------------------------------------
#define KNN_T  128
#define CAP_C  1280

__global__ void __launch_bounds__(KNN_T)
knn_cell(int N, int M)
{
    const int b   = blockIdx.y;
    const int c   = blockIdx.x;
    const int bs  = b * (G3 + 1);
    const int qs  = g_qstart[bs + c];
    const int qe  = g_qstart[bs + c + 1];
    if (qs == qe) return;

    const int cz = c / (G * G);
    const int cy = (c / G) % G;
    const int cx = c % G;

    const int pbase = b * N;
    const int qbase = b * M;
    const int tid   = threadIdx.x;

    __shared__ int    rowS[9], rowE[9];
    __shared__ float4 spts[CAP_C];
    __shared__ int    sid[CAP_C];

    if (tid < 9) {
        const int dz = tid / 3 - 1, dy = tid % 3 - 1;
        const int z = cz + dz, y = cy + dy;
        int s = 0, e = 0;
        if (z >= 0 && z < G && y >= 0 && y < G) {
            const int xlo = max(cx - 1, 0), xhi = min(cx + 1, G - 1);
            const int row = (z * G + y) * G;
            s = g_start[bs + row + xlo];
            e = g_start[bs + row + xhi + 1];
        }
        rowS[tid] = s; rowE[tid] = e;
    }
    __syncthreads();

    for (int q0 = qs; q0 < qe; q0 += KNN_T) {
        const int  myq = qbase + q0 + tid;
        const bool act = (q0 + tid) < qe;

        float qx = 0.f, qy = 0.f, qz = 0.f, q2 = 0.f;
        int qid = 0;
        if (act) {
            const float4 Q = g_qpts[myq];
            qx = Q.x; qy = Q.y; qz = Q.z; q2 = Q.w;
            qid = g_qid[myq];
        }

        float d0 = 1e30f, d1 = 1e30f, d2v = 1e30f;
        int   i0 = -1,    i1 = -1,    i2 = -1;

        auto ins = [&](float dd, int id) {
            if (dd < d2v || (dd == d2v && id < i2)) {
                if (dd < d1 || (dd == d1 && id < i1)) {
                    d2v = d1; i2 = i1;
                    if (dd < d0 || (dd == d0 && id < i0)) {
                        d1 = d0; i1 = i0; d0 = dd; i0 = id;
                    } else { d1 = dd; i1 = id; }
                } else { d2v = dd; i2 = id; }
            }
        };
        auto dist2 = [&](const float4& P) -> float {
            const float cross = __fmaf_rn(qz, P.z,
                                  __fmaf_rn(qy, P.y, __fmul_rn(qx, P.x)));
            return __fmaf_rn(-2.0f, cross, __fadd_rn(q2, P.w));
        };

        // chunked SMEM scan of the 3x3x3 box
        int row = 0, pos = rowS[0];
        while (row < 9) {
            int filled = 0;
            while (row < 9 && filled < CAP_C) {
                const int avail = rowE[row] - pos;
                const int take  = min(avail, CAP_C - filled);
                for (int i = tid; i < take; i += KNN_T) {
                    spts[filled + i] = g_pts[pbase + pos + i];
                    sid [filled + i] = g_pid[pbase + pos + i];
                }
                filled += take; pos += take;
                if (pos >= rowE[row]) { row++; if (row < 9) pos = rowS[row]; }
            }
            __syncthreads();

            if (act) {
                const int k4 = filled & ~3;
                for (int j = 0; j < k4; j += 4) {
                    const float dd0 = dist2(spts[j + 0]);
                    const float dd1 = dist2(spts[j + 1]);
                    const float dd2 = dist2(spts[j + 2]);
                    const float dd3 = dist2(spts[j + 3]);
                    const float gm  = fminf(fminf(dd0, dd1), fminf(dd2, dd3));
                    if (gm <= d2v) {            // '<=' keeps tie-break exact
                        ins(dd0, sid[j + 0]);
                        ins(dd1, sid[j + 1]);
                        ins(dd2, sid[j + 2]);
                        ins(dd3, sid[j + 3]);
                    }
                }
                for (int j = k4; j < filled; j++)
                    ins(dist2(spts[j]), sid[j]);
            }
            __syncthreads();
        }

        if (act) {
            // stop check for r=1 box; rare fallback: per-thread walk r>=2
            bool done = false;
            {
                const float fxl = (cx - 1 <= 0)     ? 1e30f : qx - (GLO + (cx - 1) * HV);
                const float fxh = (cx + 1 >= G - 1) ? 1e30f : (GLO + (cx + 2) * HV) - qx;
                const float fyl = (cy - 1 <= 0)     ? 1e30f : qy - (GLO + (cy - 1) * HV);
                const float fyh = (cy + 1 >= G - 1) ? 1e30f : (GLO + (cy + 2) * HV) - qy;
                const float fzl = (cz - 1 <= 0)     ? 1e30f : qz - (GLO + (cz - 1) * HV);
                const float fzh = (cz + 1 >= G - 1) ? 1e30f : (GLO + (cz + 2) * HV) - qz;
                const float lb  = fminf(fminf(fminf(fxl, fxh), fminf(fyl, fyh)),
                                        fminf(fzl, fzh));
                if (lb >= 1e29f) done = true;
                else if (i2 >= 0 && lb > 0.0f && d2v + MARGIN <= lb * lb) done = true;
            }

            if (!done) {
                auto process = [&](int c0, int c1) {
                    const int s = __ldg(&g_start[bs + c0]);
                    const int e = __ldg(&g_start[bs + c1 + 1]);
                    for (int p = s; p < e; p++) {
                        const float4 P  = g_pts[pbase + p];
                        ins(dist2(P), g_pid[pbase + p]);
                    }
                };
                for (int r = 2; ; r++) {
                    const int zlo = max(cz - r, 0), zhi = min(cz + r, G - 1);
                    const int ylo = max(cy - r, 0), yhi = min(cy + r, G - 1);
                    const int xlo = max(cx - r, 0), xhi = min(cx + r, G - 1);
                    for (int z = zlo; z <= zhi; z++) {
                        const bool ez = (z == cz - r) || (z == cz + r);
                        for (int y = ylo; y <= yhi; y++) {
                            const bool ey = ez || (y == cy - r) || (y == cy + r);
                            const int rw = (z * G + y) * G;
                            if (ey) {
                                process(rw + xlo, rw + xhi);
                            } else {
                                if (cx - r >= 0)     process(rw + cx - r, rw + cx - r);
                                if (cx + r <= G - 1) process(rw + cx + r, rw + cx + r);
                            }
                        }
                    }
                    const float fxl = (cx - r <= 0)     ? 1e30f : qx - (GLO + (cx - r) * HV);
                    const float fxh = (cx + r >= G - 1) ? 1e30f : (GLO + (cx + r + 1) * HV) - qx;
                    const float fyl = (cy - r <= 0)     ? 1e30f : qy - (GLO + (cy - r) * HV);
                    const float fyh = (cy + r >= G - 1) ? 1e30f : (GLO + (cy + r + 1) * HV) - qy;
                    const float fzl = (cz - r <= 0)     ? 1e30f : qz - (GLO + (cz - r) * HV);
                    const float fzh = (cz + r >= G - 1) ? 1e30f : (GLO + (cz + r + 1) * HV) - qz;
                    const float lb  = fminf(fminf(fminf(fxl, fxh), fminf(fyl, fyh)),
                                            fminf(fzl, fzh));
                    if (lb >= 1e29f) break;
                    if (i2 >= 0 && lb > 0.0f && d2v + MARGIN <= lb * lb) break;
                }
            }

            const float e0 = sqrtf(fmaxf(d0,  1e-12f));
            const float e1 = sqrtf(fmaxf(d1,  1e-12f));
            const float e2 = sqrtf(fmaxf(d2v, 1e-12f));
            const float r0 = __fdiv_rn(1.0f, __fadd_rn(e0, 1e-8f));
            const float r1 = __fdiv_rn(1.0f, __fadd_rn(e1, 1e-8f));
            const float r2 = __fdiv_rn(1.0f, __fadd_rn(e2, 1e-8f));
            const float s  = __fadd_rn(__fadd_rn(r0, r1), r2);

            const int base  = 3 * qid;          // by ORIGINAL id (R7 layout)
            g_idx[base + 0] = i0;
            g_idx[base + 1] = i1;
            g_idx[base + 2] = i2;
            g_w[base + 0]   = __fdiv_rn(r0, s);
            g_w[base + 1]   = __fdiv_rn(r1, s);
            g_w[base + 2]   = __fdiv_rn(r2, s);
        }
        __syncthreads();
    }
}

// interp: original query order (R7 layout)
__global__ void __launch_bounds__(256)
interp_kernel(const float* __restrict__ feat, float* __restrict__ out,
              int C4, int total)
{
    const int t = blockIdx.x * 256 + threadIdx.x;
    if (t >= total) return;

    const int q  = t / C4;
    const int cg = t - q * C4;

    const int   base = 3 * q;
    const int   i0 = g_idx[base + 0];
    const int   i1 = g_idx[base + 1];
    const int   i2 = g_idx[base + 2];
    const float w0 = g_w[base + 0];
    const float w1 = g_w[base + 1];
    const float w2 = g_w[base + 2];

    const float4* f = reinterpret_cast<const float4*>(feat);
    const float4 a = __ldg(f + (size_t)i0 * C4 + cg);
    const float4 b = __ldg(f + (size_t)i1 * C4 + cg);
    const float4 c = __ldg(f + (size_t)i2 * C4 + cg);

    float4 o;
    o.x = fmaf(w2, c.x, fmaf(w1, b.x, w0 * a.x));
    o.y = fmaf(w2, c.y, fmaf(w1, b.y, w0 * a.y));
    o.z = fmaf(w2, c.z, fmaf(w1, b.z, w0 * a.z));
    o.w = fmaf(w2, c.w, fmaf(w1, b.w, w0 * a.w));

    reinterpret_cast<float4*>(out)[t] = o;
}

extern "C" void kernel_launch(void* const* d_in, const int* in_sizes, int n_in,
                              void* d_out, int out_size)
{
    const float* xyz     = (const float*)d_in[0];
    const float* new_xyz = (const float*)d_in[1];
    const float* feat    = (const float*)d_in[2];

    const int B    = in_sizes[3];
    const int Ntot = in_sizes[0] / 3;
    const int Mtot = in_sizes[1] / 3;
    const int N    = Ntot / B;
    const int M    = Mtot / B;
    const int C    = in_sizes[2] / Ntot;

    const int cells = B * G3;
    const int tot   = Ntot + Mtot;

    // counters are zero on entry (static init on first call, tail-zeroed after)
    count_all<<<(tot + 255) / 256, 256>>>(xyz, new_xyz, N, Ntot, M, Mtot);   // 1
    scan_kernel<<<dim3(B, 2), 1024>>>();                                     // 2
    scatter_all<<<(tot + 255) / 256, 256>>>(xyz, new_xyz, N, Ntot, M, Mtot); // 3
    knn_cell<<<dim3(G3, B), KNN_T>>>(N, M);                                  // 4 <- profiled
    const int C4    = C / 4;
    const int total = Mtot * C4;
    interp_kernel<<<(total + 255) / 256, 256>>>(feat, (float*)d_out, C4, total); // 5
    zero_tail<<<(cells + 255) / 256, 256>>>(cells);                          // 6
}